// round 1
// baseline (speedup 1.0000x reference)
#include <cuda_runtime.h>
#include <math.h>

// Problem constants: B=16, C=512, L=1024 (32x32), 32 groups, 8 heads, ch=64.
#define NB   16
#define NC   512
#define NL   1024
#define NO3  1536

// Scratch (device globals; no allocation allowed)
__device__ float g_h  [(size_t)NB * NC  * NL];   // 32 MB  (groupnorm out)
__device__ float g_qkv[(size_t)NB * NO3 * NL];   // 96 MB
__device__ float g_a  [(size_t)NB * NC  * NL];   // 32 MB  (attention out)

// ---------------------------------------------------------------------------
// fast exp on FMA pipe (avoids MUFU throughput wall). x <= 0 expected.
// ---------------------------------------------------------------------------
__device__ __forceinline__ float fexp(float x) {
    float y = x * 1.4426950408889634f;          // log2(e)
    y = fmaxf(y, -125.0f);
    int   e = __float2int_rd(y);
    float f = y - (float)e;                      // f in [0,1)
    float p = fmaf(0.0013333558f, f, 0.0096181291f);
    p = fmaf(p, f, 0.0555041087f);
    p = fmaf(p, f, 0.2402264758f);
    p = fmaf(p, f, 0.6931471806f);
    p = fmaf(p, f, 1.0f);
    return p * __int_as_float((e + 127) << 23);
}

// ---------------------------------------------------------------------------
// GroupNorm: one block per (batch, group). group = 16 ch x 1024 = 16384 elems
// ---------------------------------------------------------------------------
__global__ __launch_bounds__(256) void gn_kernel(const float* __restrict__ x,
                                                 const float* __restrict__ w,
                                                 const float* __restrict__ b) {
    const int blk = blockIdx.x;          // 0..511
    const int bi  = blk >> 5;
    const int g   = blk & 31;
    const size_t base = ((size_t)bi * NC + (size_t)g * 16) * NL;
    const float* xp = x + base;
    float* hp = g_h + base;
    const int tid = threadIdx.x;

    float s = 0.f, s2 = 0.f;
    for (int v = tid; v < 4096; v += 256) {           // 4096 float4
        float4 q = *(const float4*)(xp + (size_t)v * 4);
        s  += q.x + q.y + q.z + q.w;
        s2 += q.x*q.x + q.y*q.y + q.z*q.z + q.w*q.w;
    }
    #pragma unroll
    for (int d = 16; d; d >>= 1) {
        s  += __shfl_xor_sync(0xffffffffu, s,  d);
        s2 += __shfl_xor_sync(0xffffffffu, s2, d);
    }
    __shared__ float rs[8], rs2[8];
    __shared__ float smean, srstd;
    if ((tid & 31) == 0) { rs[tid >> 5] = s; rs2[tid >> 5] = s2; }
    __syncthreads();
    if (tid == 0) {
        float ts = 0.f, ts2 = 0.f;
        #pragma unroll
        for (int i = 0; i < 8; i++) { ts += rs[i]; ts2 += rs2[i]; }
        float mean = ts * (1.0f / 16384.0f);
        float var  = ts2 * (1.0f / 16384.0f) - mean * mean;
        smean = mean;
        srstd = rsqrtf(var + 1e-5f);
    }
    __syncthreads();
    const float mean = smean, rstd = srstd;
    for (int v = tid; v < 4096; v += 256) {
        int c = g * 16 + (v >> 8);                     // (v*4)/1024
        float wc = w[c] * rstd, bc = b[c];
        float4 q = *(const float4*)(xp + (size_t)v * 4);
        q.x = (q.x - mean) * wc + bc;
        q.y = (q.y - mean) * wc + bc;
        q.z = (q.z - mean) * wc + bc;
        q.w = (q.w - mean) * wc + bc;
        *(float4*)(hp + (size_t)v * 4) = q;
    }
}

// ---------------------------------------------------------------------------
// Batched GEMM + bias: Y[b][m][n] = sum_k W[m][k] * X[b][k][n] + bias[m]
// 128x128 block tile, 8x8 per thread, BK=16, 256 threads.
// ---------------------------------------------------------------------------
__global__ __launch_bounds__(256) void gemm_bias(const float* __restrict__ W,
                                                 const float* __restrict__ bias,
                                                 const float* __restrict__ X,
                                                 float* __restrict__ Y,
                                                 int M, int K, int N) {
    __shared__ float As[16][128];
    __shared__ float Bs[16][128];
    const int tid   = threadIdx.x;
    const int tn    = (tid & 15) << 3;
    const int tm    = (tid >> 4) << 3;
    const int m_blk = blockIdx.y << 7;
    const int n_blk = blockIdx.x << 7;
    const float* Xb = X + (size_t)blockIdx.z * K * N;
    float*       Yb = Y + (size_t)blockIdx.z * M * N;
    const int arow = tid >> 1;
    const int acol = (tid & 1) << 3;

    float acc[8][8];
    #pragma unroll
    for (int i = 0; i < 8; i++)
        #pragma unroll
        for (int j = 0; j < 8; j++) acc[i][j] = 0.f;

    for (int k0 = 0; k0 < K; k0 += 16) {
        const float* wp = W + (size_t)(m_blk + arow) * K + (k0 + acol);
        float4 a0 = *(const float4*)wp;
        float4 a1 = *(const float4*)(wp + 4);
        As[acol + 0][arow] = a0.x; As[acol + 1][arow] = a0.y;
        As[acol + 2][arow] = a0.z; As[acol + 3][arow] = a0.w;
        As[acol + 4][arow] = a1.x; As[acol + 5][arow] = a1.y;
        As[acol + 6][arow] = a1.z; As[acol + 7][arow] = a1.w;
        #pragma unroll
        for (int r = 0; r < 2; r++) {
            int v  = (tid << 1) + r;
            int kk = v >> 5;
            int nn = (v & 31) << 2;
            *(float4*)&Bs[kk][nn] =
                *(const float4*)&Xb[(size_t)(k0 + kk) * N + n_blk + nn];
        }
        __syncthreads();
        #pragma unroll
        for (int kk = 0; kk < 16; kk++) {
            float af[8], bf[8];
            *(float4*)(af)     = *(const float4*)&As[kk][tm];
            *(float4*)(af + 4) = *(const float4*)&As[kk][tm + 4];
            *(float4*)(bf)     = *(const float4*)&Bs[kk][tn];
            *(float4*)(bf + 4) = *(const float4*)&Bs[kk][tn + 4];
            #pragma unroll
            for (int i = 0; i < 8; i++)
                #pragma unroll
                for (int j = 0; j < 8; j++)
                    acc[i][j] = fmaf(af[i], bf[j], acc[i][j]);
        }
        __syncthreads();
    }
    #pragma unroll
    for (int i = 0; i < 8; i++) {
        float bv = bias[m_blk + tm + i];
        float* yp = Yb + (size_t)(m_blk + tm + i) * N + n_blk + tn;
        float4 o0, o1;
        o0.x = acc[i][0] + bv; o0.y = acc[i][1] + bv;
        o0.z = acc[i][2] + bv; o0.w = acc[i][3] + bv;
        o1.x = acc[i][4] + bv; o1.y = acc[i][5] + bv;
        o1.z = acc[i][6] + bv; o1.w = acc[i][7] + bv;
        *(float4*)yp       = o0;
        *(float4*)(yp + 4) = o1;
    }
}

// ---------------------------------------------------------------------------
// Flash attention, fp32 SIMT. grid = (8 t-tiles, 128 heads), 256 threads.
// Per head: q,k,v are [64][1024]. S tile 128x128, online softmax.
// smem: Q/K/V [64][132] + P [128][132] + m/l/alpha rows  = 170,496 B dynamic.
// ---------------------------------------------------------------------------
#define ASTR 132
#define ATTN_SMEM ((3 * 64 * ASTR + 128 * ASTR + 3 * 128) * 4)

__global__ __launch_bounds__(256, 1) void attn_kernel() {
    extern __shared__ float sm[];
    float* Qs   = sm;                       // 64*132
    float* Ks   = Qs + 64 * ASTR;
    float* Vs   = Ks + 64 * ASTR;
    float* Ps   = Vs + 64 * ASTR;           // 128*132
    float* mrow = Ps + 128 * ASTR;
    float* lrow = mrow + 128;
    float* arow = lrow + 128;

    const int head = blockIdx.y;
    const int bi = head >> 3, hh = head & 7;
    const int t0 = blockIdx.x << 7;
    const float* qp = g_qkv + ((size_t)bi * NO3 + (size_t)hh * 192) * NL;
    const float* kp = qp + (size_t)64 * NL;
    const float* vp = kp + (size_t)64 * NL;
    const int tid = threadIdx.x;
    const int ts8 = (tid & 15) << 3;   // s offset (QK phase)
    const int tt8 = (tid >> 4) << 3;   // t offset (both phases)
    const int tc4 = (tid & 15) << 2;   // c offset (PV phase)

    // Load Q tile, pre-scaled by scale^2 = 1/sqrt(ch) = 0.125
    for (int v = tid; v < 2048; v += 256) {
        int c = v >> 5, col = (v & 31) << 2;
        float4 q = *(const float4*)&qp[(size_t)c * NL + t0 + col];
        q.x *= 0.125f; q.y *= 0.125f; q.z *= 0.125f; q.w *= 0.125f;
        *(float4*)&Qs[c * ASTR + col] = q;
    }
    if (tid < 128) { mrow[tid] = -1e30f; lrow[tid] = 0.f; }
    float acco[4][8];
    #pragma unroll
    for (int i = 0; i < 4; i++)
        #pragma unroll
        for (int j = 0; j < 8; j++) acco[i][j] = 0.f;

    for (int s0 = 0; s0 < NL; s0 += 128) {
        __syncthreads();   // prev PV done (Ks/Vs/Ps reusable); Qs/mrow visible
        for (int v = tid; v < 2048; v += 256) {
            int c = v >> 5, col = (v & 31) << 2;
            *(float4*)&Ks[c * ASTR + col] =
                *(const float4*)&kp[(size_t)c * NL + s0 + col];
            *(float4*)&Vs[c * ASTR + col] =
                *(const float4*)&vp[(size_t)c * NL + s0 + col];
        }
        __syncthreads();

        // --- S = (Q*0.125)^T K : thread computes 8t x 8s ---
        float accs[8][8];
        #pragma unroll
        for (int i = 0; i < 8; i++)
            #pragma unroll
            for (int j = 0; j < 8; j++) accs[i][j] = 0.f;
        #pragma unroll 8
        for (int k = 0; k < 64; k++) {
            float qf[8], kf[8];
            *(float4*)(qf)     = *(const float4*)&Qs[k * ASTR + tt8];
            *(float4*)(qf + 4) = *(const float4*)&Qs[k * ASTR + tt8 + 4];
            *(float4*)(kf)     = *(const float4*)&Ks[k * ASTR + ts8];
            *(float4*)(kf + 4) = *(const float4*)&Ks[k * ASTR + ts8 + 4];
            #pragma unroll
            for (int i = 0; i < 8; i++)
                #pragma unroll
                for (int j = 0; j < 8; j++)
                    accs[i][j] = fmaf(qf[i], kf[j], accs[i][j]);
        }

        // --- online softmax per row (16 lanes share each 8-row group) ---
        #pragma unroll
        for (int i = 0; i < 8; i++) {
            const int t = tt8 + i;
            float r = accs[i][0];
            #pragma unroll
            for (int j = 1; j < 8; j++) r = fmaxf(r, accs[i][j]);
            r = fmaxf(r, __shfl_xor_sync(0xffffffffu, r, 1));
            r = fmaxf(r, __shfl_xor_sync(0xffffffffu, r, 2));
            r = fmaxf(r, __shfl_xor_sync(0xffffffffu, r, 4));
            r = fmaxf(r, __shfl_xor_sync(0xffffffffu, r, 8));
            float mo = mrow[t];               // max-idempotent: race-safe
            float mn = fmaxf(mo, r);
            float sum = 0.f;
            #pragma unroll
            for (int j = 0; j < 8; j++) {
                float p = fexp(accs[i][j] - mn);
                accs[i][j] = p;
                sum += p;
            }
            sum += __shfl_xor_sync(0xffffffffu, sum, 1);
            sum += __shfl_xor_sync(0xffffffffu, sum, 2);
            sum += __shfl_xor_sync(0xffffffffu, sum, 4);
            sum += __shfl_xor_sync(0xffffffffu, sum, 8);
            if ((tid & 15) == 0) {            // unique owner per row
                float al = fexp(mo - mn);
                lrow[t] = lrow[t] * al + sum;
                mrow[t] = mn;
                arow[t] = al;
            }
            float4 p0, p1;
            p0.x = accs[i][0]; p0.y = accs[i][1]; p0.z = accs[i][2]; p0.w = accs[i][3];
            p1.x = accs[i][4]; p1.y = accs[i][5]; p1.z = accs[i][6]; p1.w = accs[i][7];
            *(float4*)&Ps[t * ASTR + ts8]     = p0;
            *(float4*)&Ps[t * ASTR + ts8 + 4] = p1;
        }
        __syncthreads();

        // --- A = A*alpha + V P^T : thread computes 4c x 8t ---
        #pragma unroll
        for (int tj = 0; tj < 8; tj++) {
            float al = arow[tt8 + tj];
            #pragma unroll
            for (int ci = 0; ci < 4; ci++) acco[ci][tj] *= al;
        }
        #pragma unroll 2
        for (int s = 0; s < 128; s += 4) {
            float4 vv[4], pp[8];
            #pragma unroll
            for (int ci = 0; ci < 4; ci++)
                vv[ci] = *(const float4*)&Vs[(tc4 + ci) * ASTR + s];
            #pragma unroll
            for (int tj = 0; tj < 8; tj++)
                pp[tj] = *(const float4*)&Ps[(tt8 + tj) * ASTR + s];
            #pragma unroll
            for (int ci = 0; ci < 4; ci++)
                #pragma unroll
                for (int tj = 0; tj < 8; tj++) {
                    float a = acco[ci][tj];
                    a = fmaf(vv[ci].x, pp[tj].x, a);
                    a = fmaf(vv[ci].y, pp[tj].y, a);
                    a = fmaf(vv[ci].z, pp[tj].z, a);
                    a = fmaf(vv[ci].w, pp[tj].w, a);
                    acco[ci][tj] = a;
                }
        }
    }

    // epilogue: divide by l, write a[b][hh*64+c][t0+t]
    float inv[8];
    #pragma unroll
    for (int tj = 0; tj < 8; tj++) inv[tj] = 1.0f / lrow[tt8 + tj];
    float* op = g_a + ((size_t)bi * NC + (size_t)hh * 64) * NL + t0;
    #pragma unroll
    for (int ci = 0; ci < 4; ci++) {
        int c = tc4 + ci;
        float4 o0, o1;
        o0.x = acco[ci][0] * inv[0]; o0.y = acco[ci][1] * inv[1];
        o0.z = acco[ci][2] * inv[2]; o0.w = acco[ci][3] * inv[3];
        o1.x = acco[ci][4] * inv[4]; o1.y = acco[ci][5] * inv[5];
        o1.z = acco[ci][6] * inv[6]; o1.w = acco[ci][7] * inv[7];
        *(float4*)&op[(size_t)c * NL + tt8]     = o0;
        *(float4*)&op[(size_t)c * NL + tt8 + 4] = o1;
    }
}

// ---------------------------------------------------------------------------
extern "C" void kernel_launch(void* const* d_in, const int* in_sizes, int n_in,
                              void* d_out, int out_size) {
    const float* x     = (const float*)d_in[0];
    const float* nw    = (const float*)d_in[1];
    const float* nb    = (const float*)d_in[2];
    const float* wqkv  = (const float*)d_in[3];
    const float* bqkv  = (const float*)d_in[4];
    const float* wproj = (const float*)d_in[5];
    const float* bproj = (const float*)d_in[6];
    float* out = (float*)d_out;

    float *ph, *pq, *pa;
    cudaGetSymbolAddress((void**)&ph, g_h);
    cudaGetSymbolAddress((void**)&pq, g_qkv);
    cudaGetSymbolAddress((void**)&pa, g_a);

    gn_kernel<<<512, 256>>>(x, nw, nb);
    gemm_bias<<<dim3(8, 12, 16), 256>>>(wqkv, bqkv, ph, pq, NO3, NC, NL);
    cudaFuncSetAttribute(attn_kernel,
                         cudaFuncAttributeMaxDynamicSharedMemorySize, ATTN_SMEM);
    attn_kernel<<<dim3(8, 128), 256, ATTN_SMEM>>>();
    gemm_bias<<<dim3(8, 4, 16), 256>>>(wproj, bproj, pa, out, NC, NC, NL);
}

// round 3
// speedup vs baseline: 2.9949x; 2.9949x over previous
#include <cuda_runtime.h>
#include <cstdint>
#include <math.h>

// Problem constants: B=16, C=512, L=1024 (32x32), 32 groups, 8 heads, ch=64.
#define NB   16
#define NC   512
#define NL   1024
#define NO3  1536

// Scratch (device globals; no allocation allowed)
__device__ float g_ht [(size_t)NB * NL * NC];    // 32 MB  groupnorm out, [b][l][c]
__device__ float g_qkv[(size_t)NB * NO3 * NL];   // 96 MB  [b][o][l]
__device__ float g_at [(size_t)NB * NL * NC];    // 32 MB  attention out, [b][l][c]

// ===========================================================================
// helpers
// ===========================================================================
__device__ __forceinline__ uint32_t cvt_tf32(float x) {
    uint32_t r;
    asm("cvt.rna.tf32.f32 %0, %1;" : "=r"(r) : "f"(x));
    return r;
}
__device__ __forceinline__ void mma_tf32(float* d, const uint32_t* a,
                                         const uint32_t* b) {
    asm volatile(
        "mma.sync.aligned.m16n8k8.row.col.f32.tf32.tf32.f32 "
        "{%0,%1,%2,%3}, {%4,%5,%6,%7}, {%8,%9}, {%0,%1,%2,%3};"
        : "+f"(d[0]), "+f"(d[1]), "+f"(d[2]), "+f"(d[3])
        : "r"(a[0]), "r"(a[1]), "r"(a[2]), "r"(a[3]), "r"(b[0]), "r"(b[1]));
}
#define CP_ASYNC16(dst, src) \
    asm volatile("cp.async.cg.shared.global [%0], [%1], 16;" \
                 :: "r"(dst), "l"(src) : "memory")
#define CP_COMMIT() asm volatile("cp.async.commit_group;" ::: "memory")
#define CP_WAIT(n)  asm volatile("cp.async.wait_group %0;" :: "n"(n) : "memory")

__device__ __forceinline__ uint32_t smem_u32(const void* p) {
    uint32_t a;
    asm("{ .reg .u64 t; cvta.to.shared.u64 t, %1; cvt.u32.u64 %0, t; }"
        : "=r"(a) : "l"(p));
    return a;
}

// fast exp on FMA pipe. x <= 0 expected.
__device__ __forceinline__ float fexp(float x) {
    float y = x * 1.4426950408889634f;
    y = fmaxf(y, -125.0f);
    int   e = __float2int_rd(y);
    float f = y - (float)e;
    float p = fmaf(0.0013333558f, f, 0.0096181291f);
    p = fmaf(p, f, 0.0555041087f);
    p = fmaf(p, f, 0.2402264758f);
    p = fmaf(p, f, 0.6931471806f);
    p = fmaf(p, f, 1.0f);
    return p * __int_as_float((e + 127) << 23);
}

// ---------------------------------------------------------------------------
// GroupNorm: one block per (batch, group); writes TRANSPOSED h_t[b][l][c].
// ---------------------------------------------------------------------------
__global__ __launch_bounds__(256) void gn_kernel(const float* __restrict__ x,
                                                 const float* __restrict__ w,
                                                 const float* __restrict__ b) {
    const int blk = blockIdx.x;
    const int bi  = blk >> 5;
    const int g   = blk & 31;
    const float* xg = x + ((size_t)bi * NC + (size_t)g * 16) * NL;
    const int tid = threadIdx.x;

    float s = 0.f, s2 = 0.f;
    for (int v = tid; v < 4096; v += 256) {
        float4 q = *(const float4*)(xg + (size_t)v * 4);
        s  += q.x + q.y + q.z + q.w;
        s2 += q.x*q.x + q.y*q.y + q.z*q.z + q.w*q.w;
    }
    #pragma unroll
    for (int d = 16; d; d >>= 1) {
        s  += __shfl_xor_sync(0xffffffffu, s,  d);
        s2 += __shfl_xor_sync(0xffffffffu, s2, d);
    }
    __shared__ float rs[8], rs2[8];
    __shared__ float smean, srstd;
    if ((tid & 31) == 0) { rs[tid >> 5] = s; rs2[tid >> 5] = s2; }
    __syncthreads();
    if (tid == 0) {
        float ts = 0.f, ts2 = 0.f;
        #pragma unroll
        for (int i = 0; i < 8; i++) { ts += rs[i]; ts2 += rs2[i]; }
        float mean = ts * (1.0f / 16384.0f);
        float var  = ts2 * (1.0f / 16384.0f) - mean * mean;
        smean = mean;
        srstd = rsqrtf(var + 1e-5f);
    }
    __syncthreads();
    const float mean = smean, rstd = srstd;

    const float* xb = x + (size_t)bi * NC * NL;
    float* ob = g_ht + (size_t)bi * NL * NC;
    #pragma unroll
    for (int t = 0; t < 4; t++) {
        int idx = tid + t * 256;
        int l   = (idx & 255) << 2;
        int cb  = g * 16 + ((idx >> 8) << 2);
        float vin[4][4];
        float wc[4], bc[4];
        #pragma unroll
        for (int i = 0; i < 4; i++) {
            *(float4*)vin[i] = *(const float4*)&xb[(size_t)(cb + i) * NL + l];
            wc[i] = w[cb + i] * rstd;
            bc[i] = b[cb + i];
        }
        #pragma unroll
        for (int j = 0; j < 4; j++) {
            float4 o;
            o.x = (vin[0][j] - mean) * wc[0] + bc[0];
            o.y = (vin[1][j] - mean) * wc[1] + bc[1];
            o.z = (vin[2][j] - mean) * wc[2] + bc[2];
            o.w = (vin[3][j] - mean) * wc[3] + bc[3];
            *(float4*)&ob[(size_t)(l + j) * NC + cb] = o;
        }
    }
}

// ---------------------------------------------------------------------------
// mma.sync tf32 GEMM + bias.
//   Y[bz][m][n] = sum_k W[m][k] * Xt[bz][n][k] + bias[m]
// 128x128 tile, BK=32, 8 warps (4m x 2n), warp tile 32x64.
// cp.async double-buffered; cvt.rna at fragment load.
// ---------------------------------------------------------------------------
#define AST 40
#define TILE_F (128 * AST)                    // floats per operand buffer
#define GEMM_SMEM (4 * TILE_F * 4)            // A0,B0,A1,B1 = 81920 B

__global__ __launch_bounds__(256, 2) void tc_gemm(const float* __restrict__ W,
                                                  const float* __restrict__ bias,
                                                  const float* __restrict__ Xt,
                                                  float* __restrict__ Y,
                                                  int M) {
    extern __shared__ float smf[];
    const int tid  = threadIdx.x;
    const int wid  = tid >> 5;
    const int lane = tid & 31;
    const int gid  = lane >> 2;
    const int tig  = lane & 3;
    const int K    = NC;
    const int n_blk = blockIdx.x << 7;
    const int m_blk = blockIdx.y << 7;
    const float* Xb = Xt + (size_t)blockIdx.z * NL * K;
    float*       Yb = Y  + (size_t)blockIdx.z * M * NL;
    const int wm = (wid >> 1) << 5;    // 0,32,64,96
    const int wn = (wid & 1) << 6;     // 0,64

    const int lrow = tid >> 3;          // base row (A and B), +32 per i
    const int lkg  = (tid & 7) << 2;    // k offset (floats)
    const uint32_t sbase = smem_u32(smf);

    float acc[2][8][4];
    #pragma unroll
    for (int a = 0; a < 2; a++)
        #pragma unroll
        for (int b = 0; b < 8; b++)
            #pragma unroll
            for (int c = 0; c < 4; c++) acc[a][b][c] = 0.f;

    const int nkt = K / 32;   // 16
    // prefetch tile 0
    {
        const float* wp = W  + (size_t)(m_blk + lrow) * K + lkg;
        const float* xp = Xb + (size_t)(n_blk + lrow) * K + lkg;
        #pragma unroll
        for (int i = 0; i < 4; i++) {
            uint32_t da = sbase + ((lrow + i * 32) * AST + lkg) * 4;
            uint32_t db = da + TILE_F * 4;
            CP_ASYNC16(da, wp + (size_t)i * 32 * K);
            CP_ASYNC16(db, xp + (size_t)i * 32 * K);
        }
        CP_COMMIT();
    }

    for (int kt = 0; kt < nkt; kt++) {
        const int bf = kt & 1;
        if (kt + 1 < nkt) {
            const int k0 = (kt + 1) << 5;
            const float* wp = W  + (size_t)(m_blk + lrow) * K + k0 + lkg;
            const float* xp = Xb + (size_t)(n_blk + lrow) * K + k0 + lkg;
            uint32_t base = sbase + (((kt + 1) & 1) ? 2 * TILE_F * 4 : 0);
            #pragma unroll
            for (int i = 0; i < 4; i++) {
                uint32_t da = base + ((lrow + i * 32) * AST + lkg) * 4;
                uint32_t db = da + TILE_F * 4;
                CP_ASYNC16(da, wp + (size_t)i * 32 * K);
                CP_ASYNC16(db, xp + (size_t)i * 32 * K);
            }
            CP_COMMIT();
            CP_WAIT(1);
        } else {
            CP_WAIT(0);
        }
        __syncthreads();

        const float* As = smf + (bf ? 2 * TILE_F : 0);
        const float* Bs = As + TILE_F;
        #pragma unroll
        for (int ks = 0; ks < 4; ks++) {
            const int k = ks << 3;
            uint32_t af[2][4];
            #pragma unroll
            for (int mt = 0; mt < 2; mt++) {
                int r0 = wm + (mt << 4) + gid;
                af[mt][0] = cvt_tf32(As[r0 * AST + k + tig]);
                af[mt][1] = cvt_tf32(As[(r0 + 8) * AST + k + tig]);
                af[mt][2] = cvt_tf32(As[r0 * AST + k + tig + 4]);
                af[mt][3] = cvt_tf32(As[(r0 + 8) * AST + k + tig + 4]);
            }
            #pragma unroll
            for (int nt = 0; nt < 8; nt++) {
                int n0 = wn + (nt << 3) + gid;
                uint32_t bfr[2];
                bfr[0] = cvt_tf32(Bs[n0 * AST + k + tig]);
                bfr[1] = cvt_tf32(Bs[n0 * AST + k + tig + 4]);
                mma_tf32(acc[0][nt], af[0], bfr);
                mma_tf32(acc[1][nt], af[1], bfr);
            }
        }
        __syncthreads();
    }

    // epilogue: bias + store (float2 per row-pair)
    #pragma unroll
    for (int mt = 0; mt < 2; mt++) {
        int m = m_blk + wm + (mt << 4) + gid;
        float bv0 = bias[m], bv1 = bias[m + 8];
        #pragma unroll
        for (int nt = 0; nt < 8; nt++) {
            int n = n_blk + wn + (nt << 3) + (tig << 1);
            float2 o0, o1;
            o0.x = acc[mt][nt][0] + bv0; o0.y = acc[mt][nt][1] + bv0;
            o1.x = acc[mt][nt][2] + bv1; o1.y = acc[mt][nt][3] + bv1;
            *(float2*)&Yb[(size_t)m * NL + n]       = o0;
            *(float2*)&Yb[(size_t)(m + 8) * NL + n] = o1;
        }
    }
}

// ---------------------------------------------------------------------------
// Flash attention with mma.sync tf32 for QK^T and PV.
// grid = (8 t-tiles, 128 heads), 256 threads (8 warps).
// Warp w owns t-rows [16w, 16w+16).
// smem: Qs/Ks [64][136] tf32, Vs [64][132] tf32, Ps [128][132] tf32,
//       m/l/alpha rows.
// ---------------------------------------------------------------------------
#define QST 136
#define VST 132
#define PST 132
#define ATTN_SMEM ((2 * 64 * QST + 64 * VST + 128 * PST + 3 * 128) * 4)

__global__ __launch_bounds__(256, 1) void attn_kernel() {
    extern __shared__ float sm[];
    float* Qs   = sm;                     // 64 x 136
    float* Ks   = Qs + 64 * QST;          // 64 x 136
    float* Vs   = Ks + 64 * QST;          // 64 x 132
    float* Ps   = Vs + 64 * VST;          // 128 x 132
    float* mrow = Ps + 128 * PST;
    float* lrow = mrow + 128;
    float* arow = lrow + 128;

    const int head = blockIdx.y;
    const int bi = head >> 3, hh = head & 7;
    const int t0 = blockIdx.x << 7;
    const float* qp = g_qkv + ((size_t)bi * NO3 + (size_t)hh * 192) * NL;
    const float* kp = qp + (size_t)64 * NL;
    const float* vp = kp + (size_t)64 * NL;
    const int tid  = threadIdx.x;
    const int wid  = tid >> 5;
    const int lane = tid & 31;
    const int gid  = lane >> 2;
    const int tig  = lane & 3;
    const int tb   = wid << 4;            // warp's t base
    const int r0   = tb + gid, r1 = r0 + 8;

    // load Q (pre-scaled by 1/sqrt(ch) = 0.125), cvt to tf32
    for (int v = tid; v < 2048; v += 256) {
        int c = v >> 5, col = (v & 31) << 2;
        float4 q = *(const float4*)&qp[(size_t)c * NL + t0 + col];
        uint4 o;
        o.x = cvt_tf32(q.x * 0.125f); o.y = cvt_tf32(q.y * 0.125f);
        o.z = cvt_tf32(q.z * 0.125f); o.w = cvt_tf32(q.w * 0.125f);
        *(uint4*)&Qs[c * QST + col] = o;
    }
    if (tid < 128) { mrow[tid] = -1e30f; lrow[tid] = 0.f; }

    float oacc[8][4];
    #pragma unroll
    for (int i = 0; i < 8; i++)
        #pragma unroll
        for (int j = 0; j < 4; j++) oacc[i][j] = 0.f;

    for (int s0 = 0; s0 < NL; s0 += 128) {
        __syncthreads();   // prev PV done; Ks/Vs/Ps reusable
        for (int v = tid; v < 2048; v += 256) {
            int c = v >> 5, col = (v & 31) << 2;
            float4 kv = *(const float4*)&kp[(size_t)c * NL + s0 + col];
            float4 vv = *(const float4*)&vp[(size_t)c * NL + s0 + col];
            uint4 ok, ov;
            ok.x = cvt_tf32(kv.x); ok.y = cvt_tf32(kv.y);
            ok.z = cvt_tf32(kv.z); ok.w = cvt_tf32(kv.w);
            ov.x = cvt_tf32(vv.x); ov.y = cvt_tf32(vv.y);
            ov.z = cvt_tf32(vv.z); ov.w = cvt_tf32(vv.w);
            *(uint4*)&Ks[c * QST + col] = ok;
            *(uint4*)&Vs[c * VST + col] = ov;
        }
        __syncthreads();

        // --- S = Q^T K : warp computes 16t x 128s via 16 n-tiles, 8 k-steps
        float sacc[16][4];
        #pragma unroll
        for (int i = 0; i < 16; i++)
            #pragma unroll
            for (int j = 0; j < 4; j++) sacc[i][j] = 0.f;
        #pragma unroll
        for (int ks = 0; ks < 8; ks++) {
            const int k = ks << 3;
            uint32_t af[4];
            af[0] = __float_as_uint(Qs[(k + tig) * QST + tb + gid]);
            af[1] = __float_as_uint(Qs[(k + tig) * QST + tb + gid + 8]);
            af[2] = __float_as_uint(Qs[(k + tig + 4) * QST + tb + gid]);
            af[3] = __float_as_uint(Qs[(k + tig + 4) * QST + tb + gid + 8]);
            #pragma unroll
            for (int nt = 0; nt < 16; nt++) {
                int sc = (nt << 3) + gid;
                uint32_t bfr[2];
                bfr[0] = __float_as_uint(Ks[(k + tig) * QST + sc]);
                bfr[1] = __float_as_uint(Ks[(k + tig + 4) * QST + sc]);
                mma_tf32(sacc[nt], af, bfr);
            }
        }

        // --- online softmax on fragments (rows r0, r1; 4 lanes share a row)
        float mx0 = -1e30f, mx1 = -1e30f;
        #pragma unroll
        for (int nt = 0; nt < 16; nt++) {
            mx0 = fmaxf(mx0, fmaxf(sacc[nt][0], sacc[nt][1]));
            mx1 = fmaxf(mx1, fmaxf(sacc[nt][2], sacc[nt][3]));
        }
        mx0 = fmaxf(mx0, __shfl_xor_sync(0xffffffffu, mx0, 1));
        mx0 = fmaxf(mx0, __shfl_xor_sync(0xffffffffu, mx0, 2));
        mx1 = fmaxf(mx1, __shfl_xor_sync(0xffffffffu, mx1, 1));
        mx1 = fmaxf(mx1, __shfl_xor_sync(0xffffffffu, mx1, 2));
        float mo0 = mrow[r0], mo1 = mrow[r1];
        float mn0 = fmaxf(mo0, mx0), mn1 = fmaxf(mo1, mx1);
        float sum0 = 0.f, sum1 = 0.f;
        #pragma unroll
        for (int nt = 0; nt < 16; nt++) {
            float p0 = fexp(sacc[nt][0] - mn0);
            float p1 = fexp(sacc[nt][1] - mn0);
            float p2 = fexp(sacc[nt][2] - mn1);
            float p3 = fexp(sacc[nt][3] - mn1);
            sum0 += p0 + p1; sum1 += p2 + p3;
            sacc[nt][0] = p0; sacc[nt][1] = p1;
            sacc[nt][2] = p2; sacc[nt][3] = p3;
        }
        sum0 += __shfl_xor_sync(0xffffffffu, sum0, 1);
        sum0 += __shfl_xor_sync(0xffffffffu, sum0, 2);
        sum1 += __shfl_xor_sync(0xffffffffu, sum1, 1);
        sum1 += __shfl_xor_sync(0xffffffffu, sum1, 2);
        if (tig == 0) {
            float al0 = fexp(mo0 - mn0), al1 = fexp(mo1 - mn1);
            lrow[r0] = lrow[r0] * al0 + sum0;
            lrow[r1] = lrow[r1] * al1 + sum1;
            mrow[r0] = mn0; mrow[r1] = mn1;
            arow[r0] = al0; arow[r1] = al1;
        }
        // write P (tf32)
        #pragma unroll
        for (int nt = 0; nt < 16; nt++) {
            int c0 = (nt << 3) + (tig << 1);
            Ps[r0 * PST + c0]     = __uint_as_float(cvt_tf32(sacc[nt][0]));
            Ps[r0 * PST + c0 + 1] = __uint_as_float(cvt_tf32(sacc[nt][1]));
            Ps[r1 * PST + c0]     = __uint_as_float(cvt_tf32(sacc[nt][2]));
            Ps[r1 * PST + c0 + 1] = __uint_as_float(cvt_tf32(sacc[nt][3]));
        }
        __syncthreads();

        // --- O = O*alpha + P V^T : warp computes 16t x 64c
        float al0 = arow[r0], al1 = arow[r1];
        #pragma unroll
        for (int nt = 0; nt < 8; nt++) {
            oacc[nt][0] *= al0; oacc[nt][1] *= al0;
            oacc[nt][2] *= al1; oacc[nt][3] *= al1;
        }
        #pragma unroll
        for (int ks = 0; ks < 16; ks++) {
            const int k = ks << 3;
            uint32_t af[4];
            af[0] = __float_as_uint(Ps[(tb + gid) * PST + k + tig]);
            af[1] = __float_as_uint(Ps[(tb + gid + 8) * PST + k + tig]);
            af[2] = __float_as_uint(Ps[(tb + gid) * PST + k + tig + 4]);
            af[3] = __float_as_uint(Ps[(tb + gid + 8) * PST + k + tig + 4]);
            #pragma unroll
            for (int nt = 0; nt < 8; nt++) {
                int cc = (nt << 3) + gid;
                uint32_t bfr[2];
                bfr[0] = __float_as_uint(Vs[cc * VST + k + tig]);
                bfr[1] = __float_as_uint(Vs[cc * VST + k + tig + 4]);
                mma_tf32(oacc[nt], af, bfr);
            }
        }
    }

    // epilogue: divide by l, write TRANSPOSED a_t[b][t0+t][hh*64 + c]
    __syncthreads();
    float inv0 = 1.0f / lrow[r0], inv1 = 1.0f / lrow[r1];
    float* op = g_at + ((size_t)bi * NL + t0) * NC + hh * 64;
    #pragma unroll
    for (int nt = 0; nt < 8; nt++) {
        int c0 = (nt << 3) + (tig << 1);
        float2 o0, o1;
        o0.x = oacc[nt][0] * inv0; o0.y = oacc[nt][1] * inv0;
        o1.x = oacc[nt][2] * inv1; o1.y = oacc[nt][3] * inv1;
        *(float2*)&op[(size_t)r0 * NC + c0] = o0;
        *(float2*)&op[(size_t)r1 * NC + c0] = o1;
    }
}

// ---------------------------------------------------------------------------
extern "C" void kernel_launch(void* const* d_in, const int* in_sizes, int n_in,
                              void* d_out, int out_size) {
    const float* x     = (const float*)d_in[0];
    const float* nw    = (const float*)d_in[1];
    const float* nb    = (const float*)d_in[2];
    const float* wqkv  = (const float*)d_in[3];
    const float* bqkv  = (const float*)d_in[4];
    const float* wproj = (const float*)d_in[5];
    const float* bproj = (const float*)d_in[6];
    float* out = (float*)d_out;

    float *pht, *pq, *pat;
    cudaGetSymbolAddress((void**)&pht, g_ht);
    cudaGetSymbolAddress((void**)&pq,  g_qkv);
    cudaGetSymbolAddress((void**)&pat, g_at);

    gn_kernel<<<512, 256>>>(x, nw, nb);

    cudaFuncSetAttribute(tc_gemm,
                         cudaFuncAttributeMaxDynamicSharedMemorySize, GEMM_SMEM);
    tc_gemm<<<dim3(8, 12, 16), 256, GEMM_SMEM>>>(wqkv, bqkv, pht, pq, NO3);

    cudaFuncSetAttribute(attn_kernel,
                         cudaFuncAttributeMaxDynamicSharedMemorySize, ATTN_SMEM);
    attn_kernel<<<dim3(8, 128), 256, ATTN_SMEM>>>();

    tc_gemm<<<dim3(8, 4, 16), 256, GEMM_SMEM>>>(wproj, bproj, pat, out, NC);
}